// round 6
// baseline (speedup 1.0000x reference)
#include <cuda_runtime.h>
#include <cuda_bf16.h>
#include <cuda_fp16.h>
#include <cstdint>

#define NNODES 100000
#define NEDGES 1600000
#define FIN  128
#define FHID 128
#define FOUT 64

// Scratch (allocation-free rule: __device__ globals)
__device__ float  g_dinv[NNODES];
__device__ int    g_deg [NNODES];
__device__ int    g_rowptr[NNODES];
__device__ int    g_cursor[NNODES];
__device__ int    g_adj [NEDGES];
__device__ __half g_Gh [NNODES * FHID];   // fp16 pre-scaled GEMM output (dinv[v]*h_v)
__device__ float  g_ACC[NNODES * FHID];   // aggregated output / next-layer input (fp32)

// ---------------- helpers ----------------

__device__ __forceinline__ uint32_t smem_u32(const void* p) {
    uint32_t a;
    asm("{ .reg .u64 t; cvta.to.shared.u64 t, %1; cvt.u32.u64 %0, t; }" : "=r"(a) : "l"(p));
    return a;
}

__device__ __forceinline__ void ldm_x4(uint32_t& r0, uint32_t& r1, uint32_t& r2, uint32_t& r3,
                                       uint32_t addr) {
    asm volatile("ldmatrix.sync.aligned.m8n8.x4.shared.b16 {%0,%1,%2,%3}, [%4];"
                 : "=r"(r0), "=r"(r1), "=r"(r2), "=r"(r3) : "r"(addr));
}

__device__ __forceinline__ void ldm_x2(uint32_t& r0, uint32_t& r1, uint32_t addr) {
    asm volatile("ldmatrix.sync.aligned.m8n8.x2.shared.b16 {%0,%1}, [%2];"
                 : "=r"(r0), "=r"(r1) : "r"(addr));
}

__device__ __forceinline__ void mma16816(float* c,
                                         uint32_t a0, uint32_t a1, uint32_t a2, uint32_t a3,
                                         uint32_t b0, uint32_t b1) {
    asm volatile("mma.sync.aligned.m16n8k16.row.col.f32.bf16.bf16.f32 "
                 "{%0,%1,%2,%3}, {%4,%5,%6,%7}, {%8,%9}, {%0,%1,%2,%3};"
                 : "+f"(c[0]), "+f"(c[1]), "+f"(c[2]), "+f"(c[3])
                 : "r"(a0), "r"(a1), "r"(a2), "r"(a3), "r"(b0), "r"(b1));
}

// ---------------- degree / norm / CSR build ----------------

__global__ void deg_zero(int* deg, int n) {
    int i = blockIdx.x * blockDim.x + threadIdx.x;
    if (i < n) deg[i] = 0;
}

__global__ void deg_count(const int* __restrict__ dst, int* deg, int e) {
    int i = blockIdx.x * blockDim.x + threadIdx.x;
    if (i < e) atomicAdd(&deg[dst[i]], 1);
}

// single-block scan: rowptr/cursor = exclusive prefix of deg; dinv = rsqrt(deg+1)
__global__ __launch_bounds__(1024) void scan_all(const int* __restrict__ deg,
                                                 float* __restrict__ dinv,
                                                 int* __restrict__ rowptr,
                                                 int* __restrict__ cursor, int n) {
    __shared__ int sm[1024];
    int t = threadIdx.x;
    int C = (n + 1023) / 1024;
    int lo = t * C;
    int hi = min(lo + C, n);
    int s = 0;
    for (int i = lo; i < hi; i++) s += deg[i];
    sm[t] = s;
    __syncthreads();
    for (int o = 1; o < 1024; o <<= 1) {
        int x = (t >= o) ? sm[t - o] : 0;
        __syncthreads();
        sm[t] += x;
        __syncthreads();
    }
    int run = (t > 0) ? sm[t - 1] : 0;    // exclusive prefix for this chunk
    for (int i = lo; i < hi; i++) {
        rowptr[i] = run;
        cursor[i] = run;
        int d = deg[i];
        run += d;
        dinv[i] = rsqrtf((float)(d + 1));
    }
}

__global__ void fill_adj(const int* __restrict__ src, const int* __restrict__ dst,
                         int* cursor, int* adj, int e) {
    int i = blockIdx.x * blockDim.x + threadIdx.x;
    if (i < e) {
        int pos = atomicAdd(&cursor[dst[i]], 1);
        adj[pos] = src[i];
    }
}

// ---------------- split-bf16 HMMA GEMM ----------------
// Gh[n,NC] = fp16( dinv[row] * ((relu?)A[n,128] @ W[128,NC]) )
// CTA tile: 128 rows x NC. 8 warps, warp w -> rows w*16..w*16+15 (full NC).
// K chunked by 64. Operands split v = hi + lo (bf16); acc += AhBh + AlBh + AhBl.

template<int NC, bool RELU>
__global__ __launch_bounds__(256) void gemm_mma(const float* __restrict__ A,
                                                const float* __restrict__ W,
                                                const float* __restrict__ dinv,
                                                __half* __restrict__ G, int n) {
    constexpr int NT = NC / 8;              // n-tiles per warp (16 or 8)
    constexpr int SAS = 72;                 // padded k-stride (bf16 elems)
    constexpr int OAH = 0;
    constexpr int OAL = 128 * SAS * 2;      // 18432
    constexpr int OBH = 2 * OAL;            // 36864
    constexpr int OBL = OBH + NC * SAS * 2;

    extern __shared__ char smraw[];
    uint32_t base = smem_u32(smraw);

    int tid = threadIdx.x;
    int w = tid >> 5;
    int lane = tid & 31;
    int row0 = blockIdx.x * 128;

    float acc[NT][4];
#pragma unroll
    for (int t = 0; t < NT; t++) {
        acc[t][0] = 0.f; acc[t][1] = 0.f; acc[t][2] = 0.f; acc[t][3] = 0.f;
    }

#pragma unroll
    for (int chunk = 0; chunk < 2; chunk++) {
        int k0 = chunk * 64;

        // ---- fill A hi/lo: 128 rows x 64 k ----
#pragma unroll
        for (int i = 0; i < 8; i++) {
            int idx4 = tid + i * 256;       // float4 slot
            int row = idx4 >> 4;
            int c4 = idx4 & 15;
            int gr = row0 + row;
            float4 v = make_float4(0.f, 0.f, 0.f, 0.f);
            if (gr < n) v = *reinterpret_cast<const float4*>(&A[(long)gr * 128 + k0 + c4 * 4]);
            if (RELU) {
                v.x = fmaxf(v.x, 0.f); v.y = fmaxf(v.y, 0.f);
                v.z = fmaxf(v.z, 0.f); v.w = fmaxf(v.w, 0.f);
            }
            __nv_bfloat16 hx = __float2bfloat16_rn(v.x);
            __nv_bfloat16 hy = __float2bfloat16_rn(v.y);
            __nv_bfloat16 hz = __float2bfloat16_rn(v.z);
            __nv_bfloat16 hw = __float2bfloat16_rn(v.w);
            __nv_bfloat162 h01 = __nv_bfloat162(hx, hy);
            __nv_bfloat162 h23 = __nv_bfloat162(hz, hw);
            __nv_bfloat162 l01 = __floats2bfloat162_rn(v.x - __bfloat162float(hx),
                                                       v.y - __bfloat162float(hy));
            __nv_bfloat162 l23 = __floats2bfloat162_rn(v.z - __bfloat162float(hz),
                                                       v.w - __bfloat162float(hw));
            int boff = (row * SAS + c4 * 4) * 2;
            *reinterpret_cast<__nv_bfloat162*>(smraw + OAH + boff)     = h01;
            *reinterpret_cast<__nv_bfloat162*>(smraw + OAH + boff + 4) = h23;
            *reinterpret_cast<__nv_bfloat162*>(smraw + OAL + boff)     = l01;
            *reinterpret_cast<__nv_bfloat162*>(smraw + OAL + boff + 4) = l23;
        }

        // ---- fill B hi/lo: W^T, NC n-rows x 64 k ----
#pragma unroll
        for (int i = 0; i < NC / 16; i++) {
            int idx4 = tid + i * 256;
            int kk = idx4 / (NC / 4);
            int n4 = idx4 % (NC / 4);
            float4 wv = *reinterpret_cast<const float4*>(&W[(long)(k0 + kk) * NC + n4 * 4]);
            float vs[4] = {wv.x, wv.y, wv.z, wv.w};
#pragma unroll
            for (int j = 0; j < 4; j++) {
                int nn = n4 * 4 + j;
                __nv_bfloat16 h = __float2bfloat16_rn(vs[j]);
                __nv_bfloat16 l = __float2bfloat16_rn(vs[j] - __bfloat162float(h));
                int boff = (nn * SAS + kk) * 2;
                *reinterpret_cast<__nv_bfloat16*>(smraw + OBH + boff) = h;
                *reinterpret_cast<__nv_bfloat16*>(smraw + OBL + boff) = l;
            }
        }
        __syncthreads();

        // ---- compute: 4 k-steps of 16 ----
#pragma unroll
        for (int ks = 0; ks < 4; ks++) {
            int kk0 = ks * 16;
            int arow = w * 16 + (lane & 15);
            int acol = kk0 + (lane >> 4) * 8;
            uint32_t aaddr = base + OAH + (uint32_t)(arow * SAS + acol) * 2;
            uint32_t aH0, aH1, aH2, aH3, aL0, aL1, aL2, aL3;
            ldm_x4(aH0, aH1, aH2, aH3, aaddr);
            ldm_x4(aL0, aL1, aL2, aL3, aaddr + (uint32_t)(OAL - OAH));

#pragma unroll
            for (int t = 0; t < NT; t++) {
                int l16 = lane & 15;
                int bn = t * 8 + (l16 & 7);
                int bk = kk0 + ((l16 >> 3) & 1) * 8;
                uint32_t baddr = base + OBH + (uint32_t)(bn * SAS + bk) * 2;
                uint32_t bH0, bH1, bL0, bL1;
                ldm_x2(bH0, bH1, baddr);
                ldm_x2(bL0, bL1, baddr + (uint32_t)(OBL - OBH));
                mma16816(acc[t], aH0, aH1, aH2, aH3, bH0, bH1);
                mma16816(acc[t], aL0, aL1, aL2, aL3, bH0, bH1);
                mma16816(acc[t], aH0, aH1, aH2, aH3, bL0, bL1);
            }
        }
        __syncthreads();
    }

    // ---- epilogue: fp16 store, scaled by dinv ----
    int r0 = row0 + w * 16 + (lane >> 2);
    int r1 = r0 + 8;
    float sc0 = (r0 < n) ? __ldg(&dinv[r0]) : 0.f;
    float sc1 = (r1 < n) ? __ldg(&dinv[r1]) : 0.f;
    int cbase = (lane & 3) * 2;
#pragma unroll
    for (int t = 0; t < NT; t++) {
        int col = t * 8 + cbase;
        if (r0 < n) {
            __half2 o = __floats2half2_rn(acc[t][0] * sc0, acc[t][1] * sc0);
            *reinterpret_cast<__half2*>(&G[(long)r0 * NC + col]) = o;
        }
        if (r1 < n) {
            __half2 o = __floats2half2_rn(acc[t][2] * sc1, acc[t][3] * sc1);
            *reinterpret_cast<__half2*>(&G[(long)r1 * NC + col]) = o;
        }
    }
}

// ---------------- gather aggregate: OUT[d] = dinv[d]*(G[d] + sum_{src in N(d)} G[src]) + b ----------------
// one warp per dst node; fp16 G rows, fp32 accumulate; x4 unroll for MLP

template<int F>
__global__ __launch_bounds__(256) void gather_k(const __half* __restrict__ G,
                                                const int* __restrict__ adj,
                                                const int* __restrict__ rowptr,
                                                const int* __restrict__ deg,
                                                const float* __restrict__ dinv,
                                                const float* __restrict__ b,
                                                float* __restrict__ OUT, int n) {
    int gw = (blockIdx.x * blockDim.x + threadIdx.x) >> 5;
    int lane = threadIdx.x & 31;
    if (gw >= n) return;

    int start = rowptr[gw];
    int cnt = deg[gw];

    if (F == 128) {
        // lane covers 4 halves (8 bytes)
        uint2 us = reinterpret_cast<const uint2*>(G + (long)gw * F)[lane];
        float2 s0 = __half22float2(*reinterpret_cast<__half2*>(&us.x));
        float2 s1 = __half22float2(*reinterpret_cast<__half2*>(&us.y));
        float4 acc = make_float4(s0.x, s0.y, s1.x, s1.y);
        for (int c = 0; c < cnt; c += 32) {
            int my = 0;
            if (c + lane < cnt) my = __ldg(&adj[start + c + lane]);
            int mend = min(32, cnt - c);
            int m = 0;
            for (; m + 4 <= mend; m += 4) {
                int i0 = __shfl_sync(0xffffffffu, my, m + 0);
                int i1 = __shfl_sync(0xffffffffu, my, m + 1);
                int i2 = __shfl_sync(0xffffffffu, my, m + 2);
                int i3 = __shfl_sync(0xffffffffu, my, m + 3);
                uint2 u0 = reinterpret_cast<const uint2*>(G + (long)i0 * F)[lane];
                uint2 u1 = reinterpret_cast<const uint2*>(G + (long)i1 * F)[lane];
                uint2 u2 = reinterpret_cast<const uint2*>(G + (long)i2 * F)[lane];
                uint2 u3 = reinterpret_cast<const uint2*>(G + (long)i3 * F)[lane];
                float2 a0 = __half22float2(*reinterpret_cast<__half2*>(&u0.x));
                float2 a1 = __half22float2(*reinterpret_cast<__half2*>(&u0.y));
                float2 b0 = __half22float2(*reinterpret_cast<__half2*>(&u1.x));
                float2 b1 = __half22float2(*reinterpret_cast<__half2*>(&u1.y));
                float2 c0 = __half22float2(*reinterpret_cast<__half2*>(&u2.x));
                float2 c1 = __half22float2(*reinterpret_cast<__half2*>(&u2.y));
                float2 d0 = __half22float2(*reinterpret_cast<__half2*>(&u3.x));
                float2 d1 = __half22float2(*reinterpret_cast<__half2*>(&u3.y));
                acc.x += a0.x + b0.x + c0.x + d0.x;
                acc.y += a0.y + b0.y + c0.y + d0.y;
                acc.z += a1.x + b1.x + c1.x + d1.x;
                acc.w += a1.y + b1.y + c1.y + d1.y;
            }
            for (; m < mend; m++) {
                int s = __shfl_sync(0xffffffffu, my, m);
                uint2 u = reinterpret_cast<const uint2*>(G + (long)s * F)[lane];
                float2 a0 = __half22float2(*reinterpret_cast<__half2*>(&u.x));
                float2 a1 = __half22float2(*reinterpret_cast<__half2*>(&u.y));
                acc.x += a0.x; acc.y += a0.y; acc.z += a1.x; acc.w += a1.y;
            }
        }
        float sc = dinv[gw];
        float4 bb = reinterpret_cast<const float4*>(b)[lane];
        float4 r;
        r.x = fmaf(acc.x, sc, bb.x);
        r.y = fmaf(acc.y, sc, bb.y);
        r.z = fmaf(acc.z, sc, bb.z);
        r.w = fmaf(acc.w, sc, bb.w);
        reinterpret_cast<float4*>(OUT + (long)gw * F)[lane] = r;
    } else {
        // F=64: lane covers 2 halves (4 bytes)
        uint32_t us = reinterpret_cast<const uint32_t*>(G + (long)gw * F)[lane];
        float2 acc = __half22float2(*reinterpret_cast<__half2*>(&us));
        for (int c = 0; c < cnt; c += 32) {
            int my = 0;
            if (c + lane < cnt) my = __ldg(&adj[start + c + lane]);
            int mend = min(32, cnt - c);
            int m = 0;
            for (; m + 4 <= mend; m += 4) {
                int i0 = __shfl_sync(0xffffffffu, my, m + 0);
                int i1 = __shfl_sync(0xffffffffu, my, m + 1);
                int i2 = __shfl_sync(0xffffffffu, my, m + 2);
                int i3 = __shfl_sync(0xffffffffu, my, m + 3);
                uint32_t u0 = reinterpret_cast<const uint32_t*>(G + (long)i0 * F)[lane];
                uint32_t u1 = reinterpret_cast<const uint32_t*>(G + (long)i1 * F)[lane];
                uint32_t u2 = reinterpret_cast<const uint32_t*>(G + (long)i2 * F)[lane];
                uint32_t u3 = reinterpret_cast<const uint32_t*>(G + (long)i3 * F)[lane];
                float2 a0 = __half22float2(*reinterpret_cast<__half2*>(&u0));
                float2 a1 = __half22float2(*reinterpret_cast<__half2*>(&u1));
                float2 a2 = __half22float2(*reinterpret_cast<__half2*>(&u2));
                float2 a3 = __half22float2(*reinterpret_cast<__half2*>(&u3));
                acc.x += a0.x + a1.x + a2.x + a3.x;
                acc.y += a0.y + a1.y + a2.y + a3.y;
            }
            for (; m < mend; m++) {
                int s = __shfl_sync(0xffffffffu, my, m);
                uint32_t u = reinterpret_cast<const uint32_t*>(G + (long)s * F)[lane];
                float2 a = __half22float2(*reinterpret_cast<__half2*>(&u));
                acc.x += a.x; acc.y += a.y;
            }
        }
        float sc = dinv[gw];
        float2 bb = reinterpret_cast<const float2*>(b)[lane];
        float2 r;
        r.x = fmaf(acc.x, sc, bb.x);
        r.y = fmaf(acc.y, sc, bb.y);
        reinterpret_cast<float2*>(OUT + (long)gw * F)[lane] = r;
    }
}

// ---------------- launch ----------------

extern "C" void kernel_launch(void* const* d_in, const int* in_sizes, int n_in,
                              void* d_out, int out_size) {
    const float* x  = (const float*)d_in[0];
    const int*   ei = (const int*)  d_in[1];
    const float* W1 = (const float*)d_in[2];
    const float* b1 = (const float*)d_in[3];
    const float* W2 = (const float*)d_in[4];
    const float* b2 = (const float*)d_in[5];
    const float* W3 = (const float*)d_in[6];
    const float* b3 = (const float*)d_in[7];
    float* out = (float*)d_out;

    int n = in_sizes[0] / FIN;
    int e = in_sizes[1] / 2;
    const int* srcp = ei;
    const int* dstp = ei + e;

    float *dinv, *ACC;
    __half* Gh;
    int *deg, *rowptr, *cursor, *adj;
    cudaGetSymbolAddress((void**)&dinv, g_dinv);
    cudaGetSymbolAddress((void**)&deg,  g_deg);
    cudaGetSymbolAddress((void**)&rowptr, g_rowptr);
    cudaGetSymbolAddress((void**)&cursor, g_cursor);
    cudaGetSymbolAddress((void**)&adj,  g_adj);
    cudaGetSymbolAddress((void**)&Gh,   g_Gh);
    cudaGetSymbolAddress((void**)&ACC,  g_ACC);

    const int T = 256;
    int gN = (n + T - 1) / T;
    int gE = (e + T - 1) / T;
    int gM = (n + 127) / 128;
    int gW = (n * 32 + T - 1) / T;

    const int SM128 = 36864 + 2 * 128 * 144;   // 73728
    const int SM64  = 36864 + 2 * 64 * 144;    // 55296
    cudaFuncSetAttribute(gemm_mma<FHID, false>, cudaFuncAttributeMaxDynamicSharedMemorySize, SM128);
    cudaFuncSetAttribute(gemm_mma<FHID, true>,  cudaFuncAttributeMaxDynamicSharedMemorySize, SM128);
    cudaFuncSetAttribute(gemm_mma<FOUT, true>,  cudaFuncAttributeMaxDynamicSharedMemorySize, SM64);

    // ---- CSR build ----
    deg_zero<<<gN, T>>>(deg, n);
    deg_count<<<gE, T>>>(dstp, deg, e);
    scan_all<<<1, 1024>>>(deg, dinv, rowptr, cursor, n);
    fill_adj<<<gE, T>>>(srcp, dstp, cursor, adj, e);

    // ---- layer 1 ----
    gemm_mma<FHID, false><<<gM, T, SM128>>>(x, W1, dinv, Gh, n);
    gather_k<FHID><<<gW, T>>>(Gh, adj, rowptr, deg, dinv, b1, ACC, n);

    // ---- layer 2 ----
    gemm_mma<FHID, true><<<gM, T, SM128>>>(ACC, W2, dinv, Gh, n);
    gather_k<FHID><<<gW, T>>>(Gh, adj, rowptr, deg, dinv, b2, ACC, n);

    // ---- layer 3 ----
    gemm_mma<FOUT, true><<<gM, T, SM64>>>(ACC, W3, dinv, Gh, n);
    gather_k<FOUT><<<gW, T>>>(Gh, adj, rowptr, deg, dinv, b3, out, n);
}

// round 7
// speedup vs baseline: 1.2471x; 1.2471x over previous
#include <cuda_runtime.h>

#define NNODES 100000
#define NEDGES 1600000
#define FIN  128
#define FHID 128
#define FOUT 64

// Scratch (allocation-free rule: __device__ globals)
__device__ float g_dinv[NNODES];
__device__ int   g_deg [NNODES];
__device__ int   g_rowptr[NNODES];
__device__ int   g_cursor[NNODES];
__device__ int   g_adj [NEDGES];
__device__ int   g_blockSums[256];
__device__ float g_G  [NNODES * FHID];   // pre-scaled GEMM output (dinv[v]*h_v)
__device__ float g_ACC[NNODES * FHID];   // aggregated output / next-layer input

// ---------------- degree / norm / CSR build ----------------

__global__ void deg_zero(int* deg, int n) {
    int i = blockIdx.x * blockDim.x + threadIdx.x;
    if (i < n) deg[i] = 0;
}

__global__ void deg_count(const int* __restrict__ dst, int* deg, int e) {
    int i = blockIdx.x * blockDim.x + threadIdx.x;
    if (i < e) atomicAdd(&deg[dst[i]], 1);
}

__global__ void dinv_fin(const int* __restrict__ deg, float* dinv, int n) {
    int i = blockIdx.x * blockDim.x + threadIdx.x;
    if (i < n) dinv[i] = rsqrtf((float)(deg[i] + 1));   // +1 self-loop
}

__global__ __launch_bounds__(512) void scan1(const int* __restrict__ deg, int* blockSums, int n) {
    __shared__ int sm[512];
    int t = threadIdx.x;
    int i = blockIdx.x * 512 + t;
    sm[t] = (i < n) ? deg[i] : 0;
    __syncthreads();
    for (int o = 256; o > 0; o >>= 1) {
        if (t < o) sm[t] += sm[t + o];
        __syncthreads();
    }
    if (t == 0) blockSums[blockIdx.x] = sm[0];
}

__global__ __launch_bounds__(256) void scan2(int* blockSums, int nb) {
    __shared__ int sm[256];
    int t = threadIdx.x;
    int v = (t < nb) ? blockSums[t] : 0;
    sm[t] = v;
    __syncthreads();
    for (int o = 1; o < 256; o <<= 1) {
        int x = (t >= o) ? sm[t - o] : 0;
        __syncthreads();
        sm[t] += x;
        __syncthreads();
    }
    if (t < nb) blockSums[t] = sm[t] - v;   // exclusive
}

__global__ __launch_bounds__(512) void scan3(const int* __restrict__ deg,
                                             const int* __restrict__ blockSums,
                                             int* rowptr, int* cursor, int n) {
    __shared__ int sm[512];
    int t = threadIdx.x;
    int i = blockIdx.x * 512 + t;
    int v = (i < n) ? deg[i] : 0;
    sm[t] = v;
    __syncthreads();
    for (int o = 1; o < 512; o <<= 1) {
        int x = (t >= o) ? sm[t - o] : 0;
        __syncthreads();
        sm[t] += x;
        __syncthreads();
    }
    if (i < n) {
        int r = blockSums[blockIdx.x] + sm[t] - v;   // exclusive
        rowptr[i] = r;
        cursor[i] = r;
    }
}

__global__ void fill_adj(const int* __restrict__ src, const int* __restrict__ dst,
                         int* cursor, int* adj, int e) {
    int i = blockIdx.x * blockDim.x + threadIdx.x;
    if (i < e) {
        int pos = atomicAdd(&cursor[dst[i]], 1);
        adj[pos] = src[i];
    }
}

// ---------------- GEMM: G[n,NC] = dinv[row] * ((relu?)A[n,128] @ W[128,NC]) ----------------
// Tile: BM=128, BN=NC, BK=16. 256 threads (tx 0..15, ty 0..15).
// Micro-tile: 8 rows (ty*8) x 8 cols as NV float4 groups at {v*64 + tx*4}.

template<int NC, bool RELU>
__global__ __launch_bounds__(256, 2) void gemm_k(const float* __restrict__ A,
                                                 const float* __restrict__ W,
                                                 const float* __restrict__ dinv,
                                                 float* __restrict__ G, int n) {
    constexpr int NV = NC / 64;   // float4 col-groups per thread (2 for 128, 1 for 64)
    __shared__ float sA[128][20];
    __shared__ float sW[16][NC];

    int tid = threadIdx.x;
    int tx = tid & 15, ty = tid >> 4;
    int row0 = blockIdx.x * 128;

    float acc[8][4 * NV];
#pragma unroll
    for (int i = 0; i < 8; i++)
#pragma unroll
        for (int j = 0; j < 4 * NV; j++) acc[i][j] = 0.0f;

#pragma unroll 1
    for (int k0 = 0; k0 < 128; k0 += 16) {
#pragma unroll
        for (int p = 0; p < 2; p++) {
            int r = p * 64 + (tid >> 2);
            int kk4 = (tid & 3) * 4;
            int gr = row0 + r;
            float4 v = make_float4(0.f, 0.f, 0.f, 0.f);
            if (gr < n) v = *reinterpret_cast<const float4*>(&A[gr * 128 + k0 + kk4]);
            if (RELU) {
                v.x = fmaxf(v.x, 0.f); v.y = fmaxf(v.y, 0.f);
                v.z = fmaxf(v.z, 0.f); v.w = fmaxf(v.w, 0.f);
            }
            sA[r][kk4 + 0] = v.x; sA[r][kk4 + 1] = v.y;
            sA[r][kk4 + 2] = v.z; sA[r][kk4 + 3] = v.w;
        }
#pragma unroll
        for (int q = 0; q < NC / 64; q++) {
            int l = tid + q * 256;
            int kk = l / (NC / 4), c4 = l % (NC / 4);
            *reinterpret_cast<float4*>(&sW[kk][c4 * 4]) =
                *reinterpret_cast<const float4*>(&W[(k0 + kk) * NC + c4 * 4]);
        }
        __syncthreads();

#pragma unroll
        for (int kk = 0; kk < 16; kk++) {
            float a[8];
#pragma unroll
            for (int i = 0; i < 8; i++) a[i] = sA[ty * 8 + i][kk];
#pragma unroll
            for (int v = 0; v < NV; v++) {
                float4 b = *reinterpret_cast<const float4*>(&sW[kk][v * 64 + tx * 4]);
#pragma unroll
                for (int i = 0; i < 8; i++) {
                    acc[i][v * 4 + 0] = fmaf(a[i], b.x, acc[i][v * 4 + 0]);
                    acc[i][v * 4 + 1] = fmaf(a[i], b.y, acc[i][v * 4 + 1]);
                    acc[i][v * 4 + 2] = fmaf(a[i], b.z, acc[i][v * 4 + 2]);
                    acc[i][v * 4 + 3] = fmaf(a[i], b.w, acc[i][v * 4 + 3]);
                }
            }
        }
        __syncthreads();
    }

#pragma unroll
    for (int i = 0; i < 8; i++) {
        int gr = row0 + ty * 8 + i;
        if (gr < n) {
            float sc = __ldg(&dinv[gr]);
#pragma unroll
            for (int v = 0; v < NV; v++) {
                float4 r = make_float4(acc[i][v * 4 + 0] * sc, acc[i][v * 4 + 1] * sc,
                                       acc[i][v * 4 + 2] * sc, acc[i][v * 4 + 3] * sc);
                *reinterpret_cast<float4*>(&G[gr * NC + v * 64 + tx * 4]) = r;
            }
        }
    }
}

// ---------------- gather aggregate: OUT[d] = dinv[d]*(G[d] + sum_{src in N(d)} G[src]) + b ----------------
// one warp per dst node; neighbor loop unrolled x8 for MLP

template<int F>
__global__ __launch_bounds__(256) void gather_k(const float* __restrict__ G,
                                                const int* __restrict__ adj,
                                                const int* __restrict__ rowptr,
                                                const int* __restrict__ deg,
                                                const float* __restrict__ dinv,
                                                const float* __restrict__ b,
                                                float* __restrict__ OUT, int n) {
    int gw = (blockIdx.x * blockDim.x + threadIdx.x) >> 5;
    int lane = threadIdx.x & 31;
    if (gw >= n) return;

    int start = rowptr[gw];
    int cnt = deg[gw];

    if (F == 128) {
        float4 acc0 = reinterpret_cast<const float4*>(G + (long)gw * F)[lane];
        float4 acc1 = make_float4(0.f, 0.f, 0.f, 0.f);
        for (int c = 0; c < cnt; c += 32) {
            int my = 0;
            if (c + lane < cnt) my = __ldg(&adj[start + c + lane]);
            int mend = min(32, cnt - c);
            int m = 0;
            for (; m + 8 <= mend; m += 8) {
                int s0 = __shfl_sync(0xffffffffu, my, m + 0);
                int s1 = __shfl_sync(0xffffffffu, my, m + 1);
                int s2 = __shfl_sync(0xffffffffu, my, m + 2);
                int s3 = __shfl_sync(0xffffffffu, my, m + 3);
                int s4 = __shfl_sync(0xffffffffu, my, m + 4);
                int s5 = __shfl_sync(0xffffffffu, my, m + 5);
                int s6 = __shfl_sync(0xffffffffu, my, m + 6);
                int s7 = __shfl_sync(0xffffffffu, my, m + 7);
                float4 v0 = reinterpret_cast<const float4*>(G + (long)s0 * F)[lane];
                float4 v1 = reinterpret_cast<const float4*>(G + (long)s1 * F)[lane];
                float4 v2 = reinterpret_cast<const float4*>(G + (long)s2 * F)[lane];
                float4 v3 = reinterpret_cast<const float4*>(G + (long)s3 * F)[lane];
                float4 v4 = reinterpret_cast<const float4*>(G + (long)s4 * F)[lane];
                float4 v5 = reinterpret_cast<const float4*>(G + (long)s5 * F)[lane];
                float4 v6 = reinterpret_cast<const float4*>(G + (long)s6 * F)[lane];
                float4 v7 = reinterpret_cast<const float4*>(G + (long)s7 * F)[lane];
                acc0.x += v0.x + v1.x + v2.x + v3.x;
                acc0.y += v0.y + v1.y + v2.y + v3.y;
                acc0.z += v0.z + v1.z + v2.z + v3.z;
                acc0.w += v0.w + v1.w + v2.w + v3.w;
                acc1.x += v4.x + v5.x + v6.x + v7.x;
                acc1.y += v4.y + v5.y + v6.y + v7.y;
                acc1.z += v4.z + v5.z + v6.z + v7.z;
                acc1.w += v4.w + v5.w + v6.w + v7.w;
            }
            for (; m < mend; m++) {
                int s = __shfl_sync(0xffffffffu, my, m);
                float4 v = reinterpret_cast<const float4*>(G + (long)s * F)[lane];
                acc0.x += v.x; acc0.y += v.y; acc0.z += v.z; acc0.w += v.w;
            }
        }
        float sc = dinv[gw];
        float4 bb = reinterpret_cast<const float4*>(b)[lane];
        float4 r;
        r.x = fmaf(acc0.x + acc1.x, sc, bb.x);
        r.y = fmaf(acc0.y + acc1.y, sc, bb.y);
        r.z = fmaf(acc0.z + acc1.z, sc, bb.z);
        r.w = fmaf(acc0.w + acc1.w, sc, bb.w);
        reinterpret_cast<float4*>(OUT + (long)gw * F)[lane] = r;
    } else {
        float2 acc0 = reinterpret_cast<const float2*>(G + (long)gw * F)[lane];
        float2 acc1 = make_float2(0.f, 0.f);
        for (int c = 0; c < cnt; c += 32) {
            int my = 0;
            if (c + lane < cnt) my = __ldg(&adj[start + c + lane]);
            int mend = min(32, cnt - c);
            int m = 0;
            for (; m + 8 <= mend; m += 8) {
                int s0 = __shfl_sync(0xffffffffu, my, m + 0);
                int s1 = __shfl_sync(0xffffffffu, my, m + 1);
                int s2 = __shfl_sync(0xffffffffu, my, m + 2);
                int s3 = __shfl_sync(0xffffffffu, my, m + 3);
                int s4 = __shfl_sync(0xffffffffu, my, m + 4);
                int s5 = __shfl_sync(0xffffffffu, my, m + 5);
                int s6 = __shfl_sync(0xffffffffu, my, m + 6);
                int s7 = __shfl_sync(0xffffffffu, my, m + 7);
                float2 v0 = reinterpret_cast<const float2*>(G + (long)s0 * F)[lane];
                float2 v1 = reinterpret_cast<const float2*>(G + (long)s1 * F)[lane];
                float2 v2 = reinterpret_cast<const float2*>(G + (long)s2 * F)[lane];
                float2 v3 = reinterpret_cast<const float2*>(G + (long)s3 * F)[lane];
                float2 v4 = reinterpret_cast<const float2*>(G + (long)s4 * F)[lane];
                float2 v5 = reinterpret_cast<const float2*>(G + (long)s5 * F)[lane];
                float2 v6 = reinterpret_cast<const float2*>(G + (long)s6 * F)[lane];
                float2 v7 = reinterpret_cast<const float2*>(G + (long)s7 * F)[lane];
                acc0.x += v0.x + v1.x + v2.x + v3.x;
                acc0.y += v0.y + v1.y + v2.y + v3.y;
                acc1.x += v4.x + v5.x + v6.x + v7.x;
                acc1.y += v4.y + v5.y + v6.y + v7.y;
            }
            for (; m < mend; m++) {
                int s = __shfl_sync(0xffffffffu, my, m);
                float2 v = reinterpret_cast<const float2*>(G + (long)s * F)[lane];
                acc0.x += v.x; acc0.y += v.y;
            }
        }
        float sc = dinv[gw];
        float2 bb = reinterpret_cast<const float2*>(b)[lane];
        float2 r;
        r.x = fmaf(acc0.x + acc1.x, sc, bb.x);
        r.y = fmaf(acc0.y + acc1.y, sc, bb.y);
        reinterpret_cast<float2*>(OUT + (long)gw * F)[lane] = r;
    }
}

// ---------------- launch ----------------

extern "C" void kernel_launch(void* const* d_in, const int* in_sizes, int n_in,
                              void* d_out, int out_size) {
    const float* x  = (const float*)d_in[0];
    const int*   ei = (const int*)  d_in[1];
    const float* W1 = (const float*)d_in[2];
    const float* b1 = (const float*)d_in[3];
    const float* W2 = (const float*)d_in[4];
    const float* b2 = (const float*)d_in[5];
    const float* W3 = (const float*)d_in[6];
    const float* b3 = (const float*)d_in[7];
    float* out = (float*)d_out;

    int n = in_sizes[0] / FIN;
    int e = in_sizes[1] / 2;
    const int* srcp = ei;
    const int* dstp = ei + e;

    float *dinv, *G, *ACC;
    int *deg, *rowptr, *cursor, *adj, *blockSums;
    cudaGetSymbolAddress((void**)&dinv, g_dinv);
    cudaGetSymbolAddress((void**)&deg,  g_deg);
    cudaGetSymbolAddress((void**)&rowptr, g_rowptr);
    cudaGetSymbolAddress((void**)&cursor, g_cursor);
    cudaGetSymbolAddress((void**)&adj,  g_adj);
    cudaGetSymbolAddress((void**)&blockSums, g_blockSums);
    cudaGetSymbolAddress((void**)&G,    g_G);
    cudaGetSymbolAddress((void**)&ACC,  g_ACC);

    const int T = 256;
    int gN = (n + T - 1) / T;
    int gE = (e + T - 1) / T;
    int gM = (n + 127) / 128;            // 128-row GEMM tiles
    int nb = (n + 511) / 512;
    int gW = (n * 32 + T - 1) / T;       // warp-per-node grids

    // side stream + events for CSR || GEMM1 overlap (created once; identical
    // launch graph on every call). No device memory involved.
    static cudaStream_t s1 = []{ cudaStream_t s; cudaStreamCreateWithFlags(&s, cudaStreamNonBlocking); return s; }();
    static cudaEvent_t evFork = []{ cudaEvent_t ev; cudaEventCreateWithFlags(&ev, cudaEventDisableTiming); return ev; }();
    static cudaEvent_t evJoin = []{ cudaEvent_t ev; cudaEventCreateWithFlags(&ev, cudaEventDisableTiming); return ev; }();

    // ---- fork: CSR build on s1, GEMM layer-1 on main stream ----
    cudaEventRecord(evFork, 0);
    cudaStreamWaitEvent(s1, evFork, 0);

    deg_zero<<<gN, T, 0, s1>>>(deg, n);
    deg_count<<<gE, T, 0, s1>>>(dstp, deg, e);
    dinv_fin<<<gN, T, 0, s1>>>(deg, dinv, n);
    scan1<<<nb, 512, 0, s1>>>(deg, blockSums, n);
    scan2<<<1, 256, 0, s1>>>(blockSums, nb);
    scan3<<<nb, 512, 0, s1>>>(deg, blockSums, rowptr, cursor, n);
    fill_adj<<<gE, T, 0, s1>>>(srcp, dstp, cursor, adj, e);
    cudaEventRecord(evJoin, s1);

    // GEMM1 without dinv scaling is impossible (needs dinv) -> keep raw GEMM,
    // scale folded into gather via per-src dinv? No: keep dependency minimal by
    // computing GEMM into G unscaled is NOT possible with current gather.
    // Instead: gemm1 needs dinv, so main stream must wait for dinv_fin only.
    // Simplest correct fork: run gemm1 AFTER join? That loses overlap.
    // Resolution: gemm writes unscaled H; gather reads use dinv[src] per edge?
    // -> Too invasive. Instead gemm1 waits on evJoin (dinv ready) but CSR's
    // fill_adj (the long pole) runs concurrently with nothing... so:
    // better split: dinv-chain on main stream, adj-chain on s1.
    // (deg needed by both; done on s1 above; main waits evJoin before gemm1.)
    cudaStreamWaitEvent(0, evJoin, 0);

    // ---- layer 1 ----
    gemm_k<FHID, false><<<gM, T>>>(x, W1, dinv, G, n);
    gather_k<FHID><<<gW, T>>>(G, adj, rowptr, deg, dinv, b1, ACC, n);

    // ---- layer 2 ----
    gemm_k<FHID, true><<<gM, T>>>(ACC, W2, dinv, G, n);
    gather_k<FHID><<<gW, T>>>(G, adj, rowptr, deg, dinv, b2, ACC, n);

    // ---- layer 3 ----
    gemm_k<FOUT, true><<<gM, T>>>(ACC, W3, dinv, G, n);
    gather_k<FOUT><<<gW, T>>>(G, adj, rowptr, deg, dinv, b3, out, n);
}

// round 8
// speedup vs baseline: 1.4160x; 1.1354x over previous
#include <cuda_runtime.h>

#define NNODES 100000
#define NEDGES 1600000
#define FIN  128
#define FHID 128
#define FOUT 64

// Scratch (allocation-free rule: __device__ globals)
__device__ float g_dinv[NNODES];
__device__ int   g_deg [NNODES];
__device__ int   g_rowptr[NNODES];
__device__ int   g_cursor[NNODES];
__device__ int   g_adj [NEDGES];
__device__ int   g_blockSums[256];
__device__ float g_G  [NNODES * FHID];   // pre-scaled GEMM output (dinv[v]*h_v)
__device__ float g_ACC[NNODES * FHID];   // aggregated output / next-layer input

// ---------------- degree / norm / CSR build ----------------

__global__ void deg_zero(int* deg, int n) {
    int i = blockIdx.x * blockDim.x + threadIdx.x;
    if (i < n) deg[i] = 0;
}

__global__ void deg_count(const int* __restrict__ dst, int* deg, int e) {
    int i = blockIdx.x * blockDim.x + threadIdx.x;
    if (i < e) atomicAdd(&deg[dst[i]], 1);
}

__global__ void dinv_fin(const int* __restrict__ deg, float* dinv, int n) {
    int i = blockIdx.x * blockDim.x + threadIdx.x;
    if (i < n) dinv[i] = rsqrtf((float)(deg[i] + 1));   // +1 self-loop
}

__global__ __launch_bounds__(512) void scan1(const int* __restrict__ deg, int* blockSums, int n) {
    __shared__ int sm[512];
    int t = threadIdx.x;
    int i = blockIdx.x * 512 + t;
    sm[t] = (i < n) ? deg[i] : 0;
    __syncthreads();
    for (int o = 256; o > 0; o >>= 1) {
        if (t < o) sm[t] += sm[t + o];
        __syncthreads();
    }
    if (t == 0) blockSums[blockIdx.x] = sm[0];
}

__global__ __launch_bounds__(256) void scan2(int* blockSums, int nb) {
    __shared__ int sm[256];
    int t = threadIdx.x;
    int v = (t < nb) ? blockSums[t] : 0;
    sm[t] = v;
    __syncthreads();
    for (int o = 1; o < 256; o <<= 1) {
        int x = (t >= o) ? sm[t - o] : 0;
        __syncthreads();
        sm[t] += x;
        __syncthreads();
    }
    if (t < nb) blockSums[t] = sm[t] - v;   // exclusive
}

__global__ __launch_bounds__(512) void scan3(const int* __restrict__ deg,
                                             const int* __restrict__ blockSums,
                                             int* rowptr, int* cursor, int n) {
    __shared__ int sm[512];
    int t = threadIdx.x;
    int i = blockIdx.x * 512 + t;
    int v = (i < n) ? deg[i] : 0;
    sm[t] = v;
    __syncthreads();
    for (int o = 1; o < 512; o <<= 1) {
        int x = (t >= o) ? sm[t - o] : 0;
        __syncthreads();
        sm[t] += x;
        __syncthreads();
    }
    if (i < n) {
        int r = blockSums[blockIdx.x] + sm[t] - v;   // exclusive
        rowptr[i] = r;
        cursor[i] = r;
    }
}

__global__ void fill_adj(const int* __restrict__ src, const int* __restrict__ dst,
                         int* cursor, int* adj, int e) {
    int i = blockIdx.x * blockDim.x + threadIdx.x;
    if (i < e) {
        int pos = atomicAdd(&cursor[dst[i]], 1);
        adj[pos] = src[i];
    }
}

// ---------------- GEMM: G[n,NC] = dinv[row] * ((relu?)A[n,128] @ W[128,NC]) ----------------
// Tile: BM=128, BN=NC, BK=16. 256 threads (tx 0..15, ty 0..15).
// Micro-tile: 8 rows (ty*8) x 8 cols as NV float4 groups at {v*64 + tx*4}.

template<int NC, bool RELU>
__global__ __launch_bounds__(256, 2) void gemm_k(const float* __restrict__ A,
                                                 const float* __restrict__ W,
                                                 const float* __restrict__ dinv,
                                                 float* __restrict__ G, int n) {
    constexpr int NV = NC / 64;   // float4 col-groups per thread (2 for 128, 1 for 64)
    __shared__ float sA[128][20];
    __shared__ float sW[16][NC];

    int tid = threadIdx.x;
    int tx = tid & 15, ty = tid >> 4;
    int row0 = blockIdx.x * 128;

    float acc[8][4 * NV];
#pragma unroll
    for (int i = 0; i < 8; i++)
#pragma unroll
        for (int j = 0; j < 4 * NV; j++) acc[i][j] = 0.0f;

#pragma unroll 1
    for (int k0 = 0; k0 < 128; k0 += 16) {
#pragma unroll
        for (int p = 0; p < 2; p++) {
            int r = p * 64 + (tid >> 2);
            int kk4 = (tid & 3) * 4;
            int gr = row0 + r;
            float4 v = make_float4(0.f, 0.f, 0.f, 0.f);
            if (gr < n) v = *reinterpret_cast<const float4*>(&A[gr * 128 + k0 + kk4]);
            if (RELU) {
                v.x = fmaxf(v.x, 0.f); v.y = fmaxf(v.y, 0.f);
                v.z = fmaxf(v.z, 0.f); v.w = fmaxf(v.w, 0.f);
            }
            sA[r][kk4 + 0] = v.x; sA[r][kk4 + 1] = v.y;
            sA[r][kk4 + 2] = v.z; sA[r][kk4 + 3] = v.w;
        }
#pragma unroll
        for (int q = 0; q < NC / 64; q++) {
            int l = tid + q * 256;
            int kk = l / (NC / 4), c4 = l % (NC / 4);
            *reinterpret_cast<float4*>(&sW[kk][c4 * 4]) =
                *reinterpret_cast<const float4*>(&W[(k0 + kk) * NC + c4 * 4]);
        }
        __syncthreads();

#pragma unroll
        for (int kk = 0; kk < 16; kk++) {
            float a[8];
#pragma unroll
            for (int i = 0; i < 8; i++) a[i] = sA[ty * 8 + i][kk];
#pragma unroll
            for (int v = 0; v < NV; v++) {
                float4 b = *reinterpret_cast<const float4*>(&sW[kk][v * 64 + tx * 4]);
#pragma unroll
                for (int i = 0; i < 8; i++) {
                    acc[i][v * 4 + 0] = fmaf(a[i], b.x, acc[i][v * 4 + 0]);
                    acc[i][v * 4 + 1] = fmaf(a[i], b.y, acc[i][v * 4 + 1]);
                    acc[i][v * 4 + 2] = fmaf(a[i], b.z, acc[i][v * 4 + 2]);
                    acc[i][v * 4 + 3] = fmaf(a[i], b.w, acc[i][v * 4 + 3]);
                }
            }
        }
        __syncthreads();
    }

#pragma unroll
    for (int i = 0; i < 8; i++) {
        int gr = row0 + ty * 8 + i;
        if (gr < n) {
            float sc = __ldg(&dinv[gr]);
#pragma unroll
            for (int v = 0; v < NV; v++) {
                float4 r = make_float4(acc[i][v * 4 + 0] * sc, acc[i][v * 4 + 1] * sc,
                                       acc[i][v * 4 + 2] * sc, acc[i][v * 4 + 3] * sc);
                *reinterpret_cast<float4*>(&G[gr * NC + v * 64 + tx * 4]) = r;
            }
        }
    }
}

// ---------------- gather aggregate: OUT[d] = dinv[d]*(G[d] + sum_{src in N(d)} G[src]) + b ----------------
// one warp per dst node; neighbor loop unrolled x4 for MLP (measured optimum)

template<int F>
__global__ __launch_bounds__(256) void gather_k(const float* __restrict__ G,
                                                const int* __restrict__ adj,
                                                const int* __restrict__ rowptr,
                                                const int* __restrict__ deg,
                                                const float* __restrict__ dinv,
                                                const float* __restrict__ b,
                                                float* __restrict__ OUT, int n) {
    int gw = (blockIdx.x * blockDim.x + threadIdx.x) >> 5;
    int lane = threadIdx.x & 31;
    if (gw >= n) return;

    int start = rowptr[gw];
    int cnt = deg[gw];

    if (F == 128) {
        float4 acc = reinterpret_cast<const float4*>(G + (long)gw * F)[lane];
        for (int c = 0; c < cnt; c += 32) {
            int my = 0;
            if (c + lane < cnt) my = __ldg(&adj[start + c + lane]);
            int mend = min(32, cnt - c);
            int m = 0;
            for (; m + 4 <= mend; m += 4) {
                int s0 = __shfl_sync(0xffffffffu, my, m + 0);
                int s1 = __shfl_sync(0xffffffffu, my, m + 1);
                int s2 = __shfl_sync(0xffffffffu, my, m + 2);
                int s3 = __shfl_sync(0xffffffffu, my, m + 3);
                float4 v0 = reinterpret_cast<const float4*>(G + (long)s0 * F)[lane];
                float4 v1 = reinterpret_cast<const float4*>(G + (long)s1 * F)[lane];
                float4 v2 = reinterpret_cast<const float4*>(G + (long)s2 * F)[lane];
                float4 v3 = reinterpret_cast<const float4*>(G + (long)s3 * F)[lane];
                acc.x += v0.x + v1.x + v2.x + v3.x;
                acc.y += v0.y + v1.y + v2.y + v3.y;
                acc.z += v0.z + v1.z + v2.z + v3.z;
                acc.w += v0.w + v1.w + v2.w + v3.w;
            }
            for (; m < mend; m++) {
                int s = __shfl_sync(0xffffffffu, my, m);
                float4 v = reinterpret_cast<const float4*>(G + (long)s * F)[lane];
                acc.x += v.x; acc.y += v.y; acc.z += v.z; acc.w += v.w;
            }
        }
        float sc = dinv[gw];
        float4 bb = reinterpret_cast<const float4*>(b)[lane];
        float4 r;
        r.x = fmaf(acc.x, sc, bb.x);
        r.y = fmaf(acc.y, sc, bb.y);
        r.z = fmaf(acc.z, sc, bb.z);
        r.w = fmaf(acc.w, sc, bb.w);
        reinterpret_cast<float4*>(OUT + (long)gw * F)[lane] = r;
    } else {
        float2 acc = reinterpret_cast<const float2*>(G + (long)gw * F)[lane];
        for (int c = 0; c < cnt; c += 32) {
            int my = 0;
            if (c + lane < cnt) my = __ldg(&adj[start + c + lane]);
            int mend = min(32, cnt - c);
            int m = 0;
            for (; m + 4 <= mend; m += 4) {
                int s0 = __shfl_sync(0xffffffffu, my, m + 0);
                int s1 = __shfl_sync(0xffffffffu, my, m + 1);
                int s2 = __shfl_sync(0xffffffffu, my, m + 2);
                int s3 = __shfl_sync(0xffffffffu, my, m + 3);
                float2 v0 = reinterpret_cast<const float2*>(G + (long)s0 * F)[lane];
                float2 v1 = reinterpret_cast<const float2*>(G + (long)s1 * F)[lane];
                float2 v2 = reinterpret_cast<const float2*>(G + (long)s2 * F)[lane];
                float2 v3 = reinterpret_cast<const float2*>(G + (long)s3 * F)[lane];
                acc.x += v0.x + v1.x + v2.x + v3.x;
                acc.y += v0.y + v1.y + v2.y + v3.y;
            }
            for (; m < mend; m++) {
                int s = __shfl_sync(0xffffffffu, my, m);
                float2 v = reinterpret_cast<const float2*>(G + (long)s * F)[lane];
                acc.x += v.x; acc.y += v.y;
            }
        }
        float sc = dinv[gw];
        float2 bb = reinterpret_cast<const float2*>(b)[lane];
        float2 r;
        r.x = fmaf(acc.x, sc, bb.x);
        r.y = fmaf(acc.y, sc, bb.y);
        reinterpret_cast<float2*>(OUT + (long)gw * F)[lane] = r;
    }
}

// ---------------- launch ----------------

extern "C" void kernel_launch(void* const* d_in, const int* in_sizes, int n_in,
                              void* d_out, int out_size) {
    const float* x  = (const float*)d_in[0];
    const int*   ei = (const int*)  d_in[1];
    const float* W1 = (const float*)d_in[2];
    const float* b1 = (const float*)d_in[3];
    const float* W2 = (const float*)d_in[4];
    const float* b2 = (const float*)d_in[5];
    const float* W3 = (const float*)d_in[6];
    const float* b3 = (const float*)d_in[7];
    float* out = (float*)d_out;

    int n = in_sizes[0] / FIN;
    int e = in_sizes[1] / 2;
    const int* srcp = ei;
    const int* dstp = ei + e;

    float *dinv, *G, *ACC;
    int *deg, *rowptr, *cursor, *adj, *blockSums;
    cudaGetSymbolAddress((void**)&dinv, g_dinv);
    cudaGetSymbolAddress((void**)&deg,  g_deg);
    cudaGetSymbolAddress((void**)&rowptr, g_rowptr);
    cudaGetSymbolAddress((void**)&cursor, g_cursor);
    cudaGetSymbolAddress((void**)&adj,  g_adj);
    cudaGetSymbolAddress((void**)&blockSums, g_blockSums);
    cudaGetSymbolAddress((void**)&G,    g_G);
    cudaGetSymbolAddress((void**)&ACC,  g_ACC);

    const int T = 256;
    int gN = (n + T - 1) / T;
    int gE = (e + T - 1) / T;
    int gM = (n + 127) / 128;            // 128-row GEMM tiles
    int nb = (n + 511) / 512;
    int gW = (n * 32 + T - 1) / T;       // warp-per-node grids

    // side stream + events: CSR scan/fill (s1) genuinely overlaps gemm1 (main).
    static cudaStream_t s1 = []{ cudaStream_t s; cudaStreamCreateWithFlags(&s, cudaStreamNonBlocking); return s; }();
    static cudaEvent_t evFork = []{ cudaEvent_t ev; cudaEventCreateWithFlags(&ev, cudaEventDisableTiming); return ev; }();
    static cudaEvent_t evJoin = []{ cudaEvent_t ev; cudaEventCreateWithFlags(&ev, cudaEventDisableTiming); return ev; }();

    // ---- serial prefix: degree + dinv (needed by gemm1 AND scan chain) ----
    deg_zero<<<gN, T>>>(deg, n);
    deg_count<<<gE, T>>>(dstp, deg, e);
    dinv_fin<<<gN, T>>>(deg, dinv, n);

    // ---- fork: scan+fill_adj on s1 || gemm1 on main ----
    cudaEventRecord(evFork, 0);
    cudaStreamWaitEvent(s1, evFork, 0);

    scan1<<<nb, 512, 0, s1>>>(deg, blockSums, n);
    scan2<<<1, 256, 0, s1>>>(blockSums, nb);
    scan3<<<nb, 512, 0, s1>>>(deg, blockSums, rowptr, cursor, n);
    fill_adj<<<gE, T, 0, s1>>>(srcp, dstp, cursor, adj, e);
    cudaEventRecord(evJoin, s1);

    gemm_k<FHID, false><<<gM, T>>>(x, W1, dinv, G, n);   // main, concurrent with s1

    // ---- join: gather needs adj/rowptr ----
    cudaStreamWaitEvent(0, evJoin, 0);

    gather_k<FHID><<<gW, T>>>(G, adj, rowptr, deg, dinv, b1, ACC, n);

    // ---- layer 2 ----
    gemm_k<FHID, true><<<gM, T>>>(ACC, W2, dinv, G, n);
    gather_k<FHID><<<gW, T>>>(G, adj, rowptr, deg, dinv, b2, ACC, n);

    // ---- layer 3 ----
    gemm_k<FOUT, true><<<gM, T>>>(ACC, W3, dinv, G, n);
    gather_k<FOUT><<<gW, T>>>(G, adj, rowptr, deg, dinv, b3, out, n);
}